// round 14
// baseline (speedup 1.0000x reference)
#include <cuda_runtime.h>
#include <math.h>
#include <stdint.h>

// Problem constants (match reference)
#define N_INPUTSC 2048
#define UNITSC    2048
#define LC        8
#define FANINC    4096
#define TOTALC    18432

#define KC      128           // partial-sum depth (k-chunks of 32 rows)
#define RPC     32            // rows per chunk
#define JT      8             // column tiles of 256
#define CPB     256           // cols per tile
#define GEMV_BLOCKS (KC * JT) // 1024
#define MAT_BLOCKS  8

// Persistent scratch (allocation-free rule: __device__ globals)
__device__ float g_partial[2][KC * UNITSC];  // ping-pong partials, 1MB each
__device__ float g_outputs[TOTALC];          // materialized state vector

// Sum the KC partials for column u of the previous layer (L2-resident).
__device__ __forceinline__ float sum_partials(const float* __restrict__ P, int u) {
    float s0 = 0.f, s1 = 0.f, s2 = 0.f, s3 = 0.f;
#pragma unroll 8
    for (int c = 0; c < KC; c += 4) {
        s0 += P[(size_t)(c    ) * UNITSC + u];
        s1 += P[(size_t)(c + 1) * UNITSC + u];
        s2 += P[(size_t)(c + 2) * UNITSC + u];
        s3 += P[(size_t)(c + 3) * UNITSC + u];
    }
    return (s0 + s1) + (s2 + s3);
}

// ---------------------------------------------------------------------------
// fused layer kernel, one launch per layer.
//  - blocks [0, 1024): gemv. Block (kc, jt): rows [kc*32,+32), cols
//    [jt*256,+256). Prologue: 32 threads gather one element each. Then each
//    warp issues cp.async.cg for its 4 rows — SKIPPING rows whose gathered
//    value is 0 (warp-uniform branch; cp.async has no consumer wait, so the
//    issue stream stays fully pipelined and dead rows generate no memory
//    requests at all). wait_group, then consume live rows from smem.
//  - blocks [1024, 1032): materialize slice `layer` into g_outputs.
// ---------------------------------------------------------------------------
__global__ __launch_bounds__(256) void layer_kernel(
    int layer,
    const float* __restrict__ x,
    const int*   __restrict__ node_inds,
    const float* __restrict__ Ws,
    const float* __restrict__ bs)
{
    const int tid  = threadIdx.x;
    const int base = layer << 11;
    const float* Pprev = g_partial[(layer + 1) & 1];
    const float* bprev = bs + (layer - 1) * UNITSC;

    if (blockIdx.x >= GEMV_BLOCKS) {
        // ---- materialize slice `layer` ----
        int u = (blockIdx.x - GEMV_BLOCKS) * 256 + tid;
        float o;
        if (layer == 0) o = x[u];
        else            o = tanhf(sum_partials(Pprev, u) + bprev[u]);
        g_outputs[base + u] = o;
        return;
    }

    const int kc = blockIdx.x >> 3;
    const int jt = blockIdx.x & 7;

    __shared__ float  sg[RPC];
    __shared__ float  tile[RPC * CPB];           // 32 KB staged W tile
    __shared__ float4 red[3][64];

    // ---- prologue: gather this chunk's 32 inputs ----
    if (tid < RPC) {
        int idx = node_inds[layer * FANINC + kc * RPC + tid];
        float v = 0.f;
        if (idx < base) {
            v = g_outputs[idx];                  // older slice, materialized
        } else if (idx < base + UNITSC) {
            int u = idx - base;                  // current slice: recompute
            if (layer == 0) v = x[u];
            else            v = tanhf(sum_partials(Pprev, u) + bprev[u]);
        }
        sg[tid] = v;
    }
    __syncthreads();

    // ---- stage live rows via cp.async (dead rows: no requests) ----
    const int wp   = tid >> 5;                   // warp 0..7: rows wp*4..+3
    const int lane = tid & 31;
    const float* Wb = Ws + ((size_t)layer * FANINC + kc * RPC) * UNITSC + jt * CPB;
    uint32_t sbase = (uint32_t)__cvta_generic_to_shared(tile);

#pragma unroll
    for (int i = 0; i < 4; ++i) {
        int r = wp * 4 + i;
        if (sg[r] != 0.f) {                      // warp-uniform skip
            const float* src = Wb + (size_t)r * UNITSC + lane * 4;
            uint32_t     dst = sbase + (uint32_t)((r * CPB + lane * 4) * 4);
            asm volatile("cp.async.cg.shared.global [%0], [%1], 16;\n"
                         :: "r"(dst), "l"(src));
            asm volatile("cp.async.cg.shared.global [%0], [%1], 16;\n"
                         :: "r"(dst + 512), "l"(src + 128));
        }
    }
    asm volatile("cp.async.commit_group;\n");
    asm volatile("cp.async.wait_group 0;\n");
    __syncthreads();

    // ---- consume: 4 groups x 8 rows x 64 float4-cols ----
    const int tx = tid & 63;
    const int tg = tid >> 6;

    float ax = 0.f, ay = 0.f, az = 0.f, aw = 0.f;
#pragma unroll
    for (int i = 0; i < 8; ++i) {
        int   r  = tg * 8 + i;
        float gk = sg[r];
        if (gk != 0.f) {                         // dead rows: smem never read
            float4 w = *reinterpret_cast<const float4*>(tile + r * CPB + tx * 4);
            ax = fmaf(gk, w.x, ax);
            ay = fmaf(gk, w.y, ay);
            az = fmaf(gk, w.z, az);
            aw = fmaf(gk, w.w, aw);
        }
    }

    if (tg > 0) red[tg - 1][tx] = make_float4(ax, ay, az, aw);
    __syncthreads();
    if (tg == 0) {
#pragma unroll
        for (int r = 0; r < 3; ++r) {
            float4 p = red[r][tx];
            ax += p.x; ay += p.y; az += p.z; aw += p.w;
        }
        *reinterpret_cast<float4*>(g_partial[layer & 1]
                                   + kc * UNITSC + jt * CPB + tx * 4) =
            make_float4(ax, ay, az, aw);
    }
}

// ---------------------------------------------------------------------------
// final: out = tanh(colsum(layer-7 partials) + b7)
// ---------------------------------------------------------------------------
__global__ __launch_bounds__(256) void final_kernel(
    const float* __restrict__ bs, float* __restrict__ out)
{
    int u = blockIdx.x * 256 + threadIdx.x;
    const float* P = g_partial[(LC - 1) & 1];
    out[u] = tanhf(sum_partials(P, u) + bs[(LC - 1) * UNITSC + u]);
}

extern "C" void kernel_launch(void* const* d_in, const int* in_sizes, int n_in,
                              void* d_out, int out_size) {
    const float* x  = (const float*)d_in[0];   // [2048] f32
    const int*   ni = (const int*)d_in[1];     // [8, 4096] i32
    const float* Ws = (const float*)d_in[2];   // [8, 4096, 2048] f32
    const float* bs = (const float*)d_in[3];   // [8, 2048] f32
    float* out = (float*)d_out;                // [2048] f32

    for (int i = 0; i < LC; ++i) {
        layer_kernel<<<GEMV_BLOCKS + MAT_BLOCKS, 256>>>(i, x, ni, Ws, bs);
    }
    final_kernel<<<UNITSC / 256, 256>>>(bs, out);
}

// round 15
// speedup vs baseline: 1.9659x; 1.9659x over previous
#include <cuda_runtime.h>
#include <math.h>

// Problem constants (match reference)
#define N_INPUTSC 2048
#define UNITSC    2048
#define LC        8
#define FANINC    4096
#define TOTALC    18432

#define KC      32            // partial-sum depth (k-chunks of 128 rows)
#define RPC     128           // rows per chunk
#define JT      16            // column tiles of 128
#define CPB     128           // cols per tile
#define GEMV_BLOCKS (KC * JT) // 512
#define MAT_BLOCKS  8         // materialization blocks appended to the grid

// Persistent scratch (allocation-free rule: __device__ globals)
__device__ float g_partial[2][KC * UNITSC];  // ping-pong partials, 256KB each
__device__ float g_outputs[TOTALC];          // materialized state vector

// Sum the KC partials for column u of the previous layer (L2-resident).
__device__ __forceinline__ float sum_partials(const float* __restrict__ P, int u) {
    float s0 = 0.f, s1 = 0.f;
#pragma unroll
    for (int c = 0; c < KC; c += 2) {
        s0 += P[(size_t)c       * UNITSC + u];
        s1 += P[(size_t)(c + 1) * UNITSC + u];
    }
    return s0 + s1;
}

// ---------------------------------------------------------------------------
// fused layer kernel, one launch per layer.
//  - blocks [0, 512): gemv. Block (kc, jt): rows [kc*128,+128), cols
//    [jt*128,+128). Prologue: 128 threads gather one element each (old
//    slices -> g_outputs; current slice -> recompute from prev partials;
//    future -> 0). Main: 8 warps x 16 rows; loads are UNCONDITIONAL (R6's
//    proven-pipelined form) but the address is a register SEL: dead rows
//    (gk==0) redirect to the chunk base row, whose 512B/warp hits L1 after
//    the first touch — DRAM traffic stays ~= live bytes only, with no branch
//    and no indirection in the load stream.
//  - blocks [512, 520): materialize slice `layer` into g_outputs.
// ---------------------------------------------------------------------------
__global__ __launch_bounds__(256) void layer_kernel(
    int layer,
    const float* __restrict__ x,
    const int*   __restrict__ node_inds,
    const float* __restrict__ Ws,
    const float* __restrict__ bs)
{
    const int tid  = threadIdx.x;
    const int base = layer << 11;
    const float* Pprev = g_partial[(layer + 1) & 1];
    const float* bprev = bs + (layer - 1) * UNITSC;

    if (blockIdx.x >= GEMV_BLOCKS) {
        // ---- materialize slice `layer` ----
        int u = (blockIdx.x - GEMV_BLOCKS) * 256 + tid;
        float o;
        if (layer == 0) o = x[u];
        else            o = tanhf(sum_partials(Pprev, u) + bprev[u]);
        g_outputs[base + u] = o;
        return;
    }

    const int kc = blockIdx.x >> 4;
    const int jt = blockIdx.x & 15;

    __shared__ float  sg[RPC];
    __shared__ float4 red[8][32];

    // Prologue: one gather element per thread (first 128 threads).
    if (tid < RPC) {
        int idx = node_inds[layer * FANINC + kc * RPC + tid];
        float v = 0.f;
        if (idx < base) {
            v = g_outputs[idx];                  // older slice, materialized
        } else if (idx < base + UNITSC) {
            int u = idx - base;                  // current slice: recompute
            if (layer == 0) v = x[u];
            else            v = tanhf(sum_partials(Pprev, u) + bprev[u]);
        }
        sg[tid] = v;
    }
    __syncthreads();

    const int tx = tid & 31;
    const int tg = tid >> 5;                     // warp id: rows tg*16..+15
    const float* Wb = Ws + ((size_t)layer * FANINC + kc * RPC + tg * 16) * UNITSC
                    + jt * CPB + tx * 4;

    float ax = 0.f, ay = 0.f, az = 0.f, aw = 0.f;
#pragma unroll
    for (int r = 0; r < 16; ++r) {
        float gk = sg[tg * 16 + r];
        // Unconditional load; dead rows redirect to the warp's base row
        // (one L1-resident line) so they cost no DRAM traffic.
        const float* p = (gk != 0.f) ? (Wb + (size_t)r * UNITSC) : Wb;
        float4 w = *reinterpret_cast<const float4*>(p);
        ax = fmaf(gk, w.x, ax);
        ay = fmaf(gk, w.y, ay);
        az = fmaf(gk, w.z, az);
        aw = fmaf(gk, w.w, aw);
    }

    red[tg][tx] = make_float4(ax, ay, az, aw);
    __syncthreads();
    if (tg == 0) {
        float4 s = red[0][tx];
#pragma unroll
        for (int r = 1; r < 8; ++r) {
            float4 p = red[r][tx];
            s.x += p.x; s.y += p.y; s.z += p.z; s.w += p.w;
        }
        *reinterpret_cast<float4*>(g_partial[layer & 1]
                                   + kc * UNITSC + jt * CPB + tx * 4) = s;
    }
}

// ---------------------------------------------------------------------------
// final: out = tanh(colsum(layer-7 partials) + b7)
// ---------------------------------------------------------------------------
__global__ __launch_bounds__(256) void final_kernel(
    const float* __restrict__ bs, float* __restrict__ out)
{
    int u = blockIdx.x * 256 + threadIdx.x;
    const float* P = g_partial[(LC - 1) & 1];
    out[u] = tanhf(sum_partials(P, u) + bs[(LC - 1) * UNITSC + u]);
}

extern "C" void kernel_launch(void* const* d_in, const int* in_sizes, int n_in,
                              void* d_out, int out_size) {
    const float* x  = (const float*)d_in[0];   // [2048] f32
    const int*   ni = (const int*)d_in[1];     // [8, 4096] i32
    const float* Ws = (const float*)d_in[2];   // [8, 4096, 2048] f32
    const float* bs = (const float*)d_in[3];   // [8, 2048] f32
    float* out = (float*)d_out;                // [2048] f32

    for (int i = 0; i < LC; ++i) {
        layer_kernel<<<GEMV_BLOCKS + MAT_BLOCKS, 256>>>(i, x, ni, Ws, bs);
    }
    final_kernel<<<UNITSC / 256, 256>>>(bs, out);
}